// round 1
// baseline (speedup 1.0000x reference)
#include <cuda_runtime.h>
#include <math.h>

// Problem constants
#define ROWS_T 4096        // B*S
#define SEQ    2048
#define NHEADS 16

// ---------------- scratch (device globals; no allocation allowed) ----------
__device__ float g_gb   [ROWS_T * 2048];   // adaln gamma/beta projection
__device__ float g_h    [ROWS_T * 1024];   // adaln output
__device__ float g_qkv  [ROWS_T * 3072];
__device__ float g_attnO[ROWS_T * 1024];
__device__ float g_x1   [ROWS_T * 1024];   // after attention residual
__device__ float g_ff   [ROWS_T * 4096];   // gelu(ffn1)

// ---------------- generic tiled GEMM:  C = epi( op(A) @ W ) ----------------
// A: (M,K) row-major, W: (K,N) row-major, C: (M,N)
// SILU_A: apply silu to A elements on load. BIAS: +bias[col]. GELU: exact gelu.
// RESID: +resid[row*N+col].
template<bool SILU_A, bool BIAS, bool GELU, bool RESID>
__global__ void __launch_bounds__(256) gemm_k(
    const float* __restrict__ A, const float* __restrict__ W,
    const float* __restrict__ bias, const float* __restrict__ resid,
    float* __restrict__ C, int M, int K, int N)
{
    __shared__ float As[16][64];   // As[k][m]
    __shared__ float Bs[16][64];   // Bs[k][n]

    const int tid = threadIdx.x;
    const int m0 = blockIdx.y * 64;
    const int n0 = blockIdx.x * 64;
    const int ty = tid >> 4;            // 0..15
    const int tx = tid & 15;            // 0..15

    const int am = tid >> 2;            // 0..63  (A row within tile)
    const int ak = (tid & 3) << 2;      // 0,4,8,12
    const int bk = tid >> 4;            // 0..15  (W row within k-tile)
    const int bn = (tid & 15) << 2;     // 0..60

    const float* Ap = A + (size_t)(m0 + am) * K + ak;
    const float* Wp = W + (size_t)bk * N + n0 + bn;

    float acc[4][4];
#pragma unroll
    for (int i = 0; i < 4; i++)
#pragma unroll
        for (int j = 0; j < 4; j++) acc[i][j] = 0.f;

    for (int k0 = 0; k0 < K; k0 += 16) {
        float4 av = *reinterpret_cast<const float4*>(Ap + k0);
        if (SILU_A) {
            av.x *= 1.f / (1.f + __expf(-av.x));
            av.y *= 1.f / (1.f + __expf(-av.y));
            av.z *= 1.f / (1.f + __expf(-av.z));
            av.w *= 1.f / (1.f + __expf(-av.w));
        }
        As[ak + 0][am] = av.x;
        As[ak + 1][am] = av.y;
        As[ak + 2][am] = av.z;
        As[ak + 3][am] = av.w;

        float4 bv = *reinterpret_cast<const float4*>(Wp + (size_t)k0 * N);
        *reinterpret_cast<float4*>(&Bs[bk][bn]) = bv;

        __syncthreads();
#pragma unroll
        for (int k = 0; k < 16; k++) {
            float4 a4 = *reinterpret_cast<const float4*>(&As[k][ty << 2]);
            float4 b4 = *reinterpret_cast<const float4*>(&Bs[k][tx << 2]);
            float aa[4] = {a4.x, a4.y, a4.z, a4.w};
            float bb[4] = {b4.x, b4.y, b4.z, b4.w};
#pragma unroll
            for (int i = 0; i < 4; i++)
#pragma unroll
                for (int j = 0; j < 4; j++) acc[i][j] += aa[i] * bb[j];
        }
        __syncthreads();
    }

#pragma unroll
    for (int i = 0; i < 4; i++) {
        const int row = m0 + (ty << 2) + i;
#pragma unroll
        for (int j = 0; j < 4; j++) {
            const int col = n0 + (tx << 2) + j;
            float v = acc[i][j];
            if (BIAS)  v += bias[col];
            if (GELU)  v = 0.5f * v * (1.f + erff(v * 0.70710678118654752f));
            if (RESID) v += resid[(size_t)row * N + col];
            C[(size_t)row * N + col] = v;
        }
    }
}

// ---------------- AdaLN: LN(x) * (1+gamma) + beta ---------------------------
// x: (4096,1024); gb: (4096,2048) [gamma | beta]; out: (4096,1024)
__global__ void __launch_bounds__(256) adaln_k(
    const float* __restrict__ x, const float* __restrict__ gb,
    float* __restrict__ out)
{
    const int row = blockIdx.x;
    const int tid = threadIdx.x;
    const float4* xr = reinterpret_cast<const float4*>(x + (size_t)row * 1024);
    float4 v = xr[tid];

    float s  = v.x + v.y + v.z + v.w;
    float ss = v.x * v.x + v.y * v.y + v.z * v.z + v.w * v.w;
#pragma unroll
    for (int o = 16; o > 0; o >>= 1) {
        s  += __shfl_xor_sync(0xffffffffu, s,  o);
        ss += __shfl_xor_sync(0xffffffffu, ss, o);
    }
    __shared__ float rs[8], rss[8];
    const int w = tid >> 5, l = tid & 31;
    if (l == 0) { rs[w] = s; rss[w] = ss; }
    __syncthreads();
    if (w == 0) {
        s  = (l < 8) ? rs[l]  : 0.f;
        ss = (l < 8) ? rss[l] : 0.f;
#pragma unroll
        for (int o = 4; o > 0; o >>= 1) {
            s  += __shfl_xor_sync(0xffffffffu, s,  o);
            ss += __shfl_xor_sync(0xffffffffu, ss, o);
        }
        if (l == 0) { rs[0] = s; rss[0] = ss; }
    }
    __syncthreads();
    const float mean = rs[0] * (1.f / 1024.f);
    const float var  = rss[0] * (1.f / 1024.f) - mean * mean;
    const float rstd = rsqrtf(var + 1e-5f);

    const float4* gr = reinterpret_cast<const float4*>(gb + (size_t)row * 2048);
    float4 gm = gr[tid];        // gamma cols tid*4..
    float4 bt = gr[256 + tid];  // beta
    float4 o;
    o.x = (v.x - mean) * rstd * (1.f + gm.x) + bt.x;
    o.y = (v.y - mean) * rstd * (1.f + gm.y) + bt.y;
    o.z = (v.z - mean) * rstd * (1.f + gm.z) + bt.z;
    o.w = (v.w - mean) * rstd * (1.f + gm.w) + bt.w;
    reinterpret_cast<float4*>(out + (size_t)row * 1024)[tid] = o;
}

// ---------------- flash attention -------------------------------------------
// qkv: (4096, 3072) rows = b*2048+s; cols: [q | k | v] each 1024, head h at h*64.
// out: (4096, 1024) same head-major layout.
// grid (32, 16, 2) = (qtile, head, batch); 256 threads.
// Thread t handles query row r = t/4, and 16-wide column group g = t%4.
#define FA_SMEM ((64*65 + 64*64 + 64*64 + 64*65) * 4)
__global__ void __launch_bounds__(256) fattn_k(
    const float* __restrict__ qkv, float* __restrict__ out)
{
    extern __shared__ float sm[];
    float* Qs = sm;                 // [64][65]
    float* Kt = sm + 64 * 65;       // [64][64] transposed: Kt[k][c]
    float* Vs = Kt + 64 * 64;       // [64][64]
    float* Ps = Vs + 64 * 64;       // [64][65]

    const int tid = threadIdx.x;
    const int b = blockIdx.z, h = blockIdx.y;
    const int q0 = blockIdx.x * 64;
    const int r = tid >> 2;         // 0..63
    const int g = tid & 3;          // 0..3
    const size_t base = (size_t)b * SEQ * 3072 + (size_t)h * 64;

    // load Q tile
#pragma unroll
    for (int i = 0; i < 4; i++) {
        int idx = tid + i * 256;
        int row = idx >> 4;
        int c4 = (idx & 15) << 2;
        float4 qv = *reinterpret_cast<const float4*>(
            qkv + base + (size_t)(q0 + row) * 3072 + c4);
        Qs[row * 65 + c4 + 0] = qv.x;
        Qs[row * 65 + c4 + 1] = qv.y;
        Qs[row * 65 + c4 + 2] = qv.z;
        Qs[row * 65 + c4 + 3] = qv.w;
    }

    float m_run = -3.0e38f, l_run = 0.f;
    float acc[16];
#pragma unroll
    for (int i = 0; i < 16; i++) acc[i] = 0.f;

    for (int t = 0; t < 32; t++) {
        const int c0 = t * 64;
        __syncthreads();   // previous tile's Kt/Vs reads done; Q visible at t=0
#pragma unroll
        for (int i = 0; i < 4; i++) {
            int idx = tid + i * 256;
            int row = idx >> 4;
            int c4 = (idx & 15) << 2;
            const float* kp = qkv + base + (size_t)(c0 + row) * 3072 + 1024 + c4;
            float4 kv = *reinterpret_cast<const float4*>(kp);
            Kt[(c4 + 0) * 64 + row] = kv.x;
            Kt[(c4 + 1) * 64 + row] = kv.y;
            Kt[(c4 + 2) * 64 + row] = kv.z;
            Kt[(c4 + 3) * 64 + row] = kv.w;
            float4 vv = *reinterpret_cast<const float4*>(kp + 1024);
            *reinterpret_cast<float4*>(&Vs[row * 64 + c4]) = vv;
        }
        __syncthreads();

        // scores: s[cc] = Q[r,:] . K[g*16+cc,:]
        float s[16];
#pragma unroll
        for (int cc = 0; cc < 16; cc++) s[cc] = 0.f;
        for (int k = 0; k < 64; k++) {
            float qv = Qs[r * 65 + k];
            const float* kp = &Kt[k * 64 + g * 16];
            float4 k0v = *reinterpret_cast<const float4*>(kp + 0);
            float4 k1v = *reinterpret_cast<const float4*>(kp + 4);
            float4 k2v = *reinterpret_cast<const float4*>(kp + 8);
            float4 k3v = *reinterpret_cast<const float4*>(kp + 12);
            s[0]  += qv * k0v.x; s[1]  += qv * k0v.y; s[2]  += qv * k0v.z; s[3]  += qv * k0v.w;
            s[4]  += qv * k1v.x; s[5]  += qv * k1v.y; s[6]  += qv * k1v.z; s[7]  += qv * k1v.w;
            s[8]  += qv * k2v.x; s[9]  += qv * k2v.y; s[10] += qv * k2v.z; s[11] += qv * k2v.w;
            s[12] += qv * k3v.x; s[13] += qv * k3v.y; s[14] += qv * k3v.z; s[15] += qv * k3v.w;
        }

        float tmax = -3.0e38f;
#pragma unroll
        for (int cc = 0; cc < 16; cc++) {
            s[cc] *= 0.125f;           // d^-0.5, d=64
            tmax = fmaxf(tmax, s[cc]);
        }
        tmax = fmaxf(tmax, __shfl_xor_sync(0xffffffffu, tmax, 1));
        tmax = fmaxf(tmax, __shfl_xor_sync(0xffffffffu, tmax, 2));
        const float mnew = fmaxf(m_run, tmax);
        const float corr = __expf(m_run - mnew);
        float tsum = 0.f;
#pragma unroll
        for (int cc = 0; cc < 16; cc++) {
            float p = __expf(s[cc] - mnew);
            s[cc] = p;
            tsum += p;
        }
        tsum += __shfl_xor_sync(0xffffffffu, tsum, 1);
        tsum += __shfl_xor_sync(0xffffffffu, tsum, 2);
        l_run = l_run * corr + tsum;
        m_run = mnew;

        // publish P row (only the 4 lanes of this row group touch Ps[r][*])
#pragma unroll
        for (int cc = 0; cc < 16; cc++) Ps[r * 65 + g * 16 + cc] = s[cc];
        __syncwarp();

#pragma unroll
        for (int i = 0; i < 16; i++) acc[i] *= corr;
        for (int c = 0; c < 64; c++) {
            float p = Ps[r * 65 + c];
            const float* vp = &Vs[c * 64 + g * 16];
            float4 v0 = *reinterpret_cast<const float4*>(vp + 0);
            float4 v1 = *reinterpret_cast<const float4*>(vp + 4);
            float4 v2 = *reinterpret_cast<const float4*>(vp + 8);
            float4 v3 = *reinterpret_cast<const float4*>(vp + 12);
            acc[0]  += p * v0.x; acc[1]  += p * v0.y; acc[2]  += p * v0.z; acc[3]  += p * v0.w;
            acc[4]  += p * v1.x; acc[5]  += p * v1.y; acc[6]  += p * v1.z; acc[7]  += p * v1.w;
            acc[8]  += p * v2.x; acc[9]  += p * v2.y; acc[10] += p * v2.z; acc[11] += p * v2.w;
            acc[12] += p * v3.x; acc[13] += p * v3.y; acc[14] += p * v3.z; acc[15] += p * v3.w;
        }
    }

    const float inv = 1.f / l_run;
    float* op = out + (size_t)(b * SEQ + q0 + r) * 1024 + h * 64 + g * 16;
    float4 o0 = {acc[0] * inv, acc[1] * inv, acc[2] * inv, acc[3] * inv};
    float4 o1 = {acc[4] * inv, acc[5] * inv, acc[6] * inv, acc[7] * inv};
    float4 o2 = {acc[8] * inv, acc[9] * inv, acc[10] * inv, acc[11] * inv};
    float4 o3 = {acc[12] * inv, acc[13] * inv, acc[14] * inv, acc[15] * inv};
    reinterpret_cast<float4*>(op)[0] = o0;
    reinterpret_cast<float4*>(op)[1] = o1;
    reinterpret_cast<float4*>(op)[2] = o2;
    reinterpret_cast<float4*>(op)[3] = o3;
}

// ---------------- launch -----------------------------------------------------
extern "C" void kernel_launch(void* const* d_in, const int* in_sizes, int n_in,
                              void* d_out, int out_size)
{
    const float* x          = (const float*)d_in[0];
    const float* cond       = (const float*)d_in[1];
    const float* p1_w       = (const float*)d_in[2];
    const float* p1_b       = (const float*)d_in[3];
    const float* qkv_w      = (const float*)d_in[4];
    const float* attn_out_w = (const float*)d_in[5];
    const float* p2_w       = (const float*)d_in[6];
    const float* p2_b       = (const float*)d_in[7];
    const float* ffn_w1     = (const float*)d_in[8];
    const float* ffn_b1     = (const float*)d_in[9];
    const float* ffn_w2     = (const float*)d_in[10];
    const float* ffn_b2     = (const float*)d_in[11];
    float* out = (float*)d_out;

    float *gb, *h, *qkvb, *attnO, *x1, *ff;
    cudaGetSymbolAddress((void**)&gb,    g_gb);
    cudaGetSymbolAddress((void**)&h,     g_h);
    cudaGetSymbolAddress((void**)&qkvb,  g_qkv);
    cudaGetSymbolAddress((void**)&attnO, g_attnO);
    cudaGetSymbolAddress((void**)&x1,    g_x1);
    cudaGetSymbolAddress((void**)&ff,    g_ff);

    cudaFuncSetAttribute(fattn_k, cudaFuncAttributeMaxDynamicSharedMemorySize,
                         FA_SMEM);

    const dim3 thr(256);
    const int M = ROWS_T;

    // 1) gb1 = silu(cond) @ p1_w + p1_b               (4096,512)x(512,2048)
    gemm_k<true, true, false, false><<<dim3(2048 / 64, M / 64), thr>>>(
        cond, p1_w, p1_b, nullptr, gb, M, 512, 2048);
    // 2) h = adaln(x, gb1)
    adaln_k<<<M, 256>>>(x, gb, h);
    // 3) qkv = h @ qkv_w                              (4096,1024)x(1024,3072)
    gemm_k<false, false, false, false><<<dim3(3072 / 64, M / 64), thr>>>(
        h, qkv_w, nullptr, nullptr, qkvb, M, 1024, 3072);
    // 4) attnO = softmax(q k^T / sqrt(d)) v
    fattn_k<<<dim3(SEQ / 64, NHEADS, 2), 256, FA_SMEM>>>(qkvb, attnO);
    // 5) x1 = x + attnO @ attn_out_w                  (4096,1024)x(1024,1024)
    gemm_k<false, false, false, true><<<dim3(1024 / 64, M / 64), thr>>>(
        attnO, attn_out_w, nullptr, x, x1, M, 1024, 1024);
    // 6) gb2 = silu(cond) @ p2_w + p2_b
    gemm_k<true, true, false, false><<<dim3(2048 / 64, M / 64), thr>>>(
        cond, p2_w, p2_b, nullptr, gb, M, 512, 2048);
    // 7) h = adaln(x1, gb2)
    adaln_k<<<M, 256>>>(x1, gb, h);
    // 8) ff = gelu(h @ ffn_w1 + ffn_b1)               (4096,1024)x(1024,4096)
    gemm_k<false, true, true, false><<<dim3(4096 / 64, M / 64), thr>>>(
        h, ffn_w1, ffn_b1, nullptr, ff, M, 1024, 4096);
    // 9) out = x1 + ff @ ffn_w2 + ffn_b2              (4096,4096)x(4096,1024)
    gemm_k<false, true, false, true><<<dim3(1024 / 64, M / 64), thr>>>(
        ff, ffn_w2, ffn_b2, x1, out, M, 4096, 1024);
}

// round 2
// speedup vs baseline: 1.5234x; 1.5234x over previous
#include <cuda_runtime.h>
#include <math.h>
#include <stdint.h>

#define ROWS_T 4096
#define SEQ    2048
#define NHEADS 16

// ---------------- scratch ----------------------------------------------------
__device__ float g_gb   [ROWS_T * 2048];
__device__ float g_h    [ROWS_T * 1024];
__device__ float g_qkv  [ROWS_T * 3072];
__device__ float g_attnO[ROWS_T * 1024];
__device__ float g_x1   [ROWS_T * 1024];
__device__ float g_ff   [ROWS_T * 4096];
__device__ float g_sc   [ROWS_T * 512];     // rtf32(silu(cond))
__device__ float g_w1   [512 * 2048];
__device__ float g_wqkv [1024 * 3072];
__device__ float g_wao  [1024 * 1024];
__device__ float g_w2   [512 * 2048];
__device__ float g_wf1  [1024 * 4096];
__device__ float g_wf2  [4096 * 1024];

__device__ __forceinline__ float rtf32(float x) {
    float y;
    asm("cvt.rna.tf32.f32 %0, %1;" : "=f"(y) : "f"(x));
    return y;
}

// ---------------- prep kernels ----------------------------------------------
__global__ void round_k(const float* __restrict__ in, float* __restrict__ out, int n4) {
    int i = blockIdx.x * blockDim.x + threadIdx.x;
    if (i < n4) {
        float4 v = reinterpret_cast<const float4*>(in)[i];
        v.x = rtf32(v.x); v.y = rtf32(v.y); v.z = rtf32(v.z); v.w = rtf32(v.w);
        reinterpret_cast<float4*>(out)[i] = v;
    }
}
__global__ void silu_round_k(const float* __restrict__ in, float* __restrict__ out, int n4) {
    int i = blockIdx.x * blockDim.x + threadIdx.x;
    if (i < n4) {
        float4 v = reinterpret_cast<const float4*>(in)[i];
        v.x = rtf32(v.x / (1.f + __expf(-v.x)));
        v.y = rtf32(v.y / (1.f + __expf(-v.y)));
        v.z = rtf32(v.z / (1.f + __expf(-v.z)));
        v.w = rtf32(v.w / (1.f + __expf(-v.w)));
        reinterpret_cast<float4*>(out)[i] = v;
    }
}

// ---------------- tf32 tensor-core GEMM --------------------------------------
// C(M,N) = epi( A(M,K) @ W(K,N) ); A,W pre-rounded to tf32.
// BM=128 BN=128 BK=32, 256 threads, 8 warps (2x4), warp tile 64x32.
#define AS_STG (128 * 36)
#define BS_STG (32 * 136)
#define GEMM_SMEM ((2 * AS_STG + 2 * BS_STG) * 4)

#define MMA_TF32(d, a, b) asm volatile( \
    "mma.sync.aligned.m16n8k8.row.col.f32.tf32.tf32.f32 " \
    "{%0,%1,%2,%3}, {%4,%5,%6,%7}, {%8,%9}, {%0,%1,%2,%3};" \
    : "+f"(d[0]), "+f"(d[1]), "+f"(d[2]), "+f"(d[3]) \
    : "r"(a[0]), "r"(a[1]), "r"(a[2]), "r"(a[3]), "r"(b[0]), "r"(b[1]))

#define CP16(dst_u32, src_ptr) asm volatile( \
    "cp.async.ca.shared.global [%0], [%1], 16;" :: "r"(dst_u32), "l"(src_ptr))

template<bool BIAS, bool GELU, bool RESID, bool ROUND>
__global__ void __launch_bounds__(256, 2) gemm_tc(
    const float* __restrict__ A, const float* __restrict__ W,
    const float* __restrict__ bias, const float* __restrict__ resid,
    float* __restrict__ C, int M, int K, int N)
{
    extern __shared__ float sm[];
    float* As = sm;                    // [2][128][36]
    float* Bs = sm + 2 * AS_STG;       // [2][32][136]

    uint32_t smem_base;
    asm("{.reg .u64 t; cvta.to.shared.u64 t, %1; cvt.u32.u64 %0, t;}"
        : "=r"(smem_base) : "l"(sm));
    const uint32_t asb = smem_base;
    const uint32_t bsb = smem_base + 2 * AS_STG * 4;

    const int tid  = threadIdx.x;
    const int lane = tid & 31;
    const int warp = tid >> 5;
    const int wm = (warp & 1) * 64;
    const int wn = (warp >> 1) * 32;
    const int gid = lane >> 2;
    const int tig = lane & 3;

    const int m0 = blockIdx.y * 128;
    const int n0 = blockIdx.x * 128;

    const int a_m = tid >> 3;          // 0..31
    const int a_k = (tid & 7) << 2;    // 0..28
    const int b_k = tid >> 5;          // 0..7
    const int b_n = (tid & 31) << 2;   // 0..124

    float acc[4][4][4];
#pragma unroll
    for (int i = 0; i < 4; i++)
#pragma unroll
        for (int j = 0; j < 4; j++)
#pragma unroll
            for (int r = 0; r < 4; r++) acc[i][j][r] = 0.f;

    const int nt = K >> 5;

    // issue tile 0 -> stage 0
#pragma unroll
    for (int i = 0; i < 4; i++) {
        CP16(asb + ((a_m + i * 32) * 36 + a_k) * 4,
             A + (size_t)(m0 + a_m + i * 32) * K + a_k);
        CP16(bsb + ((b_k + i * 8) * 136 + b_n) * 4,
             W + (size_t)(b_k + i * 8) * N + n0 + b_n);
    }
    asm volatile("cp.async.commit_group;");

    for (int t = 0; t < nt; t++) {
        const int cur = t & 1;
        if (t + 1 < nt) {
            const int nk0 = (t + 1) << 5;
            const int st = cur ^ 1;
#pragma unroll
            for (int i = 0; i < 4; i++) {
                CP16(asb + (st * AS_STG + (a_m + i * 32) * 36 + a_k) * 4,
                     A + (size_t)(m0 + a_m + i * 32) * K + nk0 + a_k);
                CP16(bsb + (st * BS_STG + (b_k + i * 8) * 136 + b_n) * 4,
                     W + (size_t)(nk0 + b_k + i * 8) * N + n0 + b_n);
            }
            asm volatile("cp.async.commit_group;");
            asm volatile("cp.async.wait_group 1;");
        } else {
            asm volatile("cp.async.wait_group 0;");
        }
        __syncthreads();

        const float* Asw = As + cur * AS_STG + wm * 36;
        const float* Bsw = Bs + cur * BS_STG + wn;
#pragma unroll
        for (int s = 0; s < 4; s++) {
            uint32_t af[4][4], bf[4][2];
#pragma unroll
            for (int mt = 0; mt < 4; mt++) {
                const float* p = Asw + (mt * 16 + gid) * 36 + s * 8 + tig;
                af[mt][0] = __float_as_uint(p[0]);
                af[mt][1] = __float_as_uint(p[8 * 36]);
                af[mt][2] = __float_as_uint(p[4]);
                af[mt][3] = __float_as_uint(p[8 * 36 + 4]);
            }
#pragma unroll
            for (int ntile = 0; ntile < 4; ntile++) {
                const float* p = Bsw + (s * 8 + tig) * 136 + ntile * 8 + gid;
                bf[ntile][0] = __float_as_uint(p[0]);
                bf[ntile][1] = __float_as_uint(p[4 * 136]);
            }
#pragma unroll
            for (int mt = 0; mt < 4; mt++)
#pragma unroll
                for (int ntile = 0; ntile < 4; ntile++)
                    MMA_TF32(acc[mt][ntile], af[mt], bf[ntile]);
        }
        __syncthreads();
    }

    // epilogue
#pragma unroll
    for (int mt = 0; mt < 4; mt++) {
        const int r0 = m0 + wm + mt * 16 + gid;
#pragma unroll
        for (int ntile = 0; ntile < 4; ntile++) {
            const int col = n0 + wn + ntile * 8 + 2 * tig;
            float b0 = 0.f, b1 = 0.f;
            if (BIAS) { b0 = bias[col]; b1 = bias[col + 1]; }
#pragma unroll
            for (int half = 0; half < 2; half++) {
                const int row = r0 + half * 8;
                float v0 = acc[mt][ntile][half * 2 + 0] + b0;
                float v1 = acc[mt][ntile][half * 2 + 1] + b1;
                if (GELU) {
                    v0 = 0.5f * v0 * (1.f + erff(v0 * 0.70710678118654752f));
                    v1 = 0.5f * v1 * (1.f + erff(v1 * 0.70710678118654752f));
                }
                if (RESID) {
                    v0 += resid[(size_t)row * N + col];
                    v1 += resid[(size_t)row * N + col + 1];
                }
                if (ROUND) { v0 = rtf32(v0); v1 = rtf32(v1); }
                float2 o = {v0, v1};
                *reinterpret_cast<float2*>(C + (size_t)row * N + col) = o;
            }
        }
    }
}

// ---------------- AdaLN (emits tf32-rounded output) --------------------------
__global__ void __launch_bounds__(256) adaln_k(
    const float* __restrict__ x, const float* __restrict__ gb,
    float* __restrict__ out)
{
    const int row = blockIdx.x;
    const int tid = threadIdx.x;
    const float4* xr = reinterpret_cast<const float4*>(x + (size_t)row * 1024);
    float4 v = xr[tid];

    float s  = v.x + v.y + v.z + v.w;
    float ss = v.x * v.x + v.y * v.y + v.z * v.z + v.w * v.w;
#pragma unroll
    for (int o = 16; o > 0; o >>= 1) {
        s  += __shfl_xor_sync(0xffffffffu, s,  o);
        ss += __shfl_xor_sync(0xffffffffu, ss, o);
    }
    __shared__ float rs[8], rss[8];
    const int w = tid >> 5, l = tid & 31;
    if (l == 0) { rs[w] = s; rss[w] = ss; }
    __syncthreads();
    if (w == 0) {
        s  = (l < 8) ? rs[l]  : 0.f;
        ss = (l < 8) ? rss[l] : 0.f;
#pragma unroll
        for (int o = 4; o > 0; o >>= 1) {
            s  += __shfl_xor_sync(0xffffffffu, s,  o);
            ss += __shfl_xor_sync(0xffffffffu, ss, o);
        }
        if (l == 0) { rs[0] = s; rss[0] = ss; }
    }
    __syncthreads();
    const float mean = rs[0] * (1.f / 1024.f);
    const float var  = rss[0] * (1.f / 1024.f) - mean * mean;
    const float rstd = rsqrtf(var + 1e-5f);

    const float4* gr = reinterpret_cast<const float4*>(gb + (size_t)row * 2048);
    float4 gm = gr[tid];
    float4 bt = gr[256 + tid];
    float4 o;
    o.x = rtf32((v.x - mean) * rstd * (1.f + gm.x) + bt.x);
    o.y = rtf32((v.y - mean) * rstd * (1.f + gm.y) + bt.y);
    o.z = rtf32((v.z - mean) * rstd * (1.f + gm.z) + bt.z);
    o.w = rtf32((v.w - mean) * rstd * (1.f + gm.w) + bt.w);
    reinterpret_cast<float4*>(out + (size_t)row * 1024)[tid] = o;
}

// ---------------- flash attention (fp32, rounded output) ---------------------
#define FA_SMEM ((64*65 + 64*64 + 64*64 + 64*65) * 4)
__global__ void __launch_bounds__(256) fattn_k(
    const float* __restrict__ qkv, float* __restrict__ out)
{
    extern __shared__ float sm[];
    float* Qs = sm;
    float* Kt = sm + 64 * 65;
    float* Vs = Kt + 64 * 64;
    float* Ps = Vs + 64 * 64;

    const int tid = threadIdx.x;
    const int b = blockIdx.z, h = blockIdx.y;
    const int q0 = blockIdx.x * 64;
    const int r = tid >> 2;
    const int g = tid & 3;
    const size_t base = (size_t)b * SEQ * 3072 + (size_t)h * 64;

#pragma unroll
    for (int i = 0; i < 4; i++) {
        int idx = tid + i * 256;
        int row = idx >> 4;
        int c4 = (idx & 15) << 2;
        float4 qv = *reinterpret_cast<const float4*>(
            qkv + base + (size_t)(q0 + row) * 3072 + c4);
        Qs[row * 65 + c4 + 0] = qv.x;
        Qs[row * 65 + c4 + 1] = qv.y;
        Qs[row * 65 + c4 + 2] = qv.z;
        Qs[row * 65 + c4 + 3] = qv.w;
    }

    float m_run = -3.0e38f, l_run = 0.f;
    float acc[16];
#pragma unroll
    for (int i = 0; i < 16; i++) acc[i] = 0.f;

    for (int t = 0; t < 32; t++) {
        const int c0 = t * 64;
        __syncthreads();
#pragma unroll
        for (int i = 0; i < 4; i++) {
            int idx = tid + i * 256;
            int row = idx >> 4;
            int c4 = (idx & 15) << 2;
            const float* kp = qkv + base + (size_t)(c0 + row) * 3072 + 1024 + c4;
            float4 kv = *reinterpret_cast<const float4*>(kp);
            Kt[(c4 + 0) * 64 + row] = kv.x;
            Kt[(c4 + 1) * 64 + row] = kv.y;
            Kt[(c4 + 2) * 64 + row] = kv.z;
            Kt[(c4 + 3) * 64 + row] = kv.w;
            float4 vv = *reinterpret_cast<const float4*>(kp + 1024);
            *reinterpret_cast<float4*>(&Vs[row * 64 + c4]) = vv;
        }
        __syncthreads();

        float s[16];
#pragma unroll
        for (int cc = 0; cc < 16; cc++) s[cc] = 0.f;
        for (int k = 0; k < 64; k++) {
            float qv = Qs[r * 65 + k];
            const float* kp = &Kt[k * 64 + g * 16];
            float4 k0v = *reinterpret_cast<const float4*>(kp + 0);
            float4 k1v = *reinterpret_cast<const float4*>(kp + 4);
            float4 k2v = *reinterpret_cast<const float4*>(kp + 8);
            float4 k3v = *reinterpret_cast<const float4*>(kp + 12);
            s[0]  += qv * k0v.x; s[1]  += qv * k0v.y; s[2]  += qv * k0v.z; s[3]  += qv * k0v.w;
            s[4]  += qv * k1v.x; s[5]  += qv * k1v.y; s[6]  += qv * k1v.z; s[7]  += qv * k1v.w;
            s[8]  += qv * k2v.x; s[9]  += qv * k2v.y; s[10] += qv * k2v.z; s[11] += qv * k2v.w;
            s[12] += qv * k3v.x; s[13] += qv * k3v.y; s[14] += qv * k3v.z; s[15] += qv * k3v.w;
        }

        float tmax = -3.0e38f;
#pragma unroll
        for (int cc = 0; cc < 16; cc++) {
            s[cc] *= 0.125f;
            tmax = fmaxf(tmax, s[cc]);
        }
        tmax = fmaxf(tmax, __shfl_xor_sync(0xffffffffu, tmax, 1));
        tmax = fmaxf(tmax, __shfl_xor_sync(0xffffffffu, tmax, 2));
        const float mnew = fmaxf(m_run, tmax);
        const float corr = __expf(m_run - mnew);
        float tsum = 0.f;
#pragma unroll
        for (int cc = 0; cc < 16; cc++) {
            float p = __expf(s[cc] - mnew);
            s[cc] = p;
            tsum += p;
        }
        tsum += __shfl_xor_sync(0xffffffffu, tsum, 1);
        tsum += __shfl_xor_sync(0xffffffffu, tsum, 2);
        l_run = l_run * corr + tsum;
        m_run = mnew;

#pragma unroll
        for (int cc = 0; cc < 16; cc++) Ps[r * 65 + g * 16 + cc] = s[cc];
        __syncwarp();

#pragma unroll
        for (int i = 0; i < 16; i++) acc[i] *= corr;
        for (int c = 0; c < 64; c++) {
            float p = Ps[r * 65 + c];
            const float* vp = &Vs[c * 64 + g * 16];
            float4 v0 = *reinterpret_cast<const float4*>(vp + 0);
            float4 v1 = *reinterpret_cast<const float4*>(vp + 4);
            float4 v2 = *reinterpret_cast<const float4*>(vp + 8);
            float4 v3 = *reinterpret_cast<const float4*>(vp + 12);
            acc[0]  += p * v0.x; acc[1]  += p * v0.y; acc[2]  += p * v0.z; acc[3]  += p * v0.w;
            acc[4]  += p * v1.x; acc[5]  += p * v1.y; acc[6]  += p * v1.z; acc[7]  += p * v1.w;
            acc[8]  += p * v2.x; acc[9]  += p * v2.y; acc[10] += p * v2.z; acc[11] += p * v2.w;
            acc[12] += p * v3.x; acc[13] += p * v3.y; acc[14] += p * v3.z; acc[15] += p * v3.w;
        }
    }

    const float inv = 1.f / l_run;
    float* op = out + (size_t)(b * SEQ + q0 + r) * 1024 + h * 64 + g * 16;
#pragma unroll
    for (int i = 0; i < 4; i++) {
        float4 o = {rtf32(acc[i * 4 + 0] * inv), rtf32(acc[i * 4 + 1] * inv),
                    rtf32(acc[i * 4 + 2] * inv), rtf32(acc[i * 4 + 3] * inv)};
        reinterpret_cast<float4*>(op)[i] = o;
    }
}

// ---------------- launch -----------------------------------------------------
extern "C" void kernel_launch(void* const* d_in, const int* in_sizes, int n_in,
                              void* d_out, int out_size)
{
    const float* x          = (const float*)d_in[0];
    const float* cond       = (const float*)d_in[1];
    const float* p1_w       = (const float*)d_in[2];
    const float* p1_b       = (const float*)d_in[3];
    const float* qkv_w      = (const float*)d_in[4];
    const float* attn_out_w = (const float*)d_in[5];
    const float* p2_w       = (const float*)d_in[6];
    const float* p2_b       = (const float*)d_in[7];
    const float* ffn_w1     = (const float*)d_in[8];
    const float* ffn_b1     = (const float*)d_in[9];
    const float* ffn_w2     = (const float*)d_in[10];
    const float* ffn_b2     = (const float*)d_in[11];
    float* out = (float*)d_out;

    float *gb, *h, *qkvb, *attnO, *x1, *ff, *sc;
    float *w1, *wqkv, *wao, *w2, *wf1, *wf2;
    cudaGetSymbolAddress((void**)&gb,    g_gb);
    cudaGetSymbolAddress((void**)&h,     g_h);
    cudaGetSymbolAddress((void**)&qkvb,  g_qkv);
    cudaGetSymbolAddress((void**)&attnO, g_attnO);
    cudaGetSymbolAddress((void**)&x1,    g_x1);
    cudaGetSymbolAddress((void**)&ff,    g_ff);
    cudaGetSymbolAddress((void**)&sc,    g_sc);
    cudaGetSymbolAddress((void**)&w1,    g_w1);
    cudaGetSymbolAddress((void**)&wqkv,  g_wqkv);
    cudaGetSymbolAddress((void**)&wao,   g_wao);
    cudaGetSymbolAddress((void**)&w2,    g_w2);
    cudaGetSymbolAddress((void**)&wf1,   g_wf1);
    cudaGetSymbolAddress((void**)&wf2,   g_wf2);

    cudaFuncSetAttribute(fattn_k, cudaFuncAttributeMaxDynamicSharedMemorySize, FA_SMEM);
    cudaFuncSetAttribute(gemm_tc<true,false,false,false>,
                         cudaFuncAttributeMaxDynamicSharedMemorySize, GEMM_SMEM);
    cudaFuncSetAttribute(gemm_tc<false,false,false,false>,
                         cudaFuncAttributeMaxDynamicSharedMemorySize, GEMM_SMEM);
    cudaFuncSetAttribute(gemm_tc<false,false,true,false>,
                         cudaFuncAttributeMaxDynamicSharedMemorySize, GEMM_SMEM);
    cudaFuncSetAttribute(gemm_tc<true,true,false,true>,
                         cudaFuncAttributeMaxDynamicSharedMemorySize, GEMM_SMEM);
    cudaFuncSetAttribute(gemm_tc<true,false,true,false>,
                         cudaFuncAttributeMaxDynamicSharedMemorySize, GEMM_SMEM);

    const int M = ROWS_T;
    const dim3 thr(256);

    // prep: round weights to tf32, silu+round cond
    round_k<<<(512*2048/4 + 255)/256, 256>>>(p1_w, w1, 512*2048/4);
    round_k<<<(1024*3072/4 + 255)/256, 256>>>(qkv_w, wqkv, 1024*3072/4);
    round_k<<<(1024*1024/4 + 255)/256, 256>>>(attn_out_w, wao, 1024*1024/4);
    round_k<<<(512*2048/4 + 255)/256, 256>>>(p2_w, w2, 512*2048/4);
    round_k<<<(1024*4096/4 + 255)/256, 256>>>(ffn_w1, wf1, 1024*4096/4);
    round_k<<<(4096*1024/4 + 255)/256, 256>>>(ffn_w2, wf2, 4096*1024/4);
    silu_round_k<<<(M*512/4 + 255)/256, 256>>>(cond, sc, M*512/4);

    // 1) gb = sc @ w1 + p1_b
    gemm_tc<true,false,false,false><<<dim3(2048/128, M/128), thr, GEMM_SMEM>>>(
        sc, w1, p1_b, nullptr, gb, M, 512, 2048);
    // 2) h = adaln(x, gb)  (tf32-rounded)
    adaln_k<<<M, 256>>>(x, gb, h);
    // 3) qkv = h @ wqkv
    gemm_tc<false,false,false,false><<<dim3(3072/128, M/128), thr, GEMM_SMEM>>>(
        h, wqkv, nullptr, nullptr, qkvb, M, 1024, 3072);
    // 4) attnO = attention(qkv)  (tf32-rounded)
    fattn_k<<<dim3(SEQ/64, NHEADS, 2), 256, FA_SMEM>>>(qkvb, attnO);
    // 5) x1 = x + attnO @ wao
    gemm_tc<false,false,true,false><<<dim3(1024/128, M/128), thr, GEMM_SMEM>>>(
        attnO, wao, nullptr, x, x1, M, 1024, 1024);
    // 6) gb = sc @ w2 + p2_b
    gemm_tc<true,false,false,false><<<dim3(2048/128, M/128), thr, GEMM_SMEM>>>(
        sc, w2, p2_b, nullptr, gb, M, 512, 2048);
    // 7) h = adaln(x1, gb)
    adaln_k<<<M, 256>>>(x1, gb, h);
    // 8) ff = rtf32(gelu(h @ wf1 + ffn_b1))
    gemm_tc<true,true,false,true><<<dim3(4096/128, M/128), thr, GEMM_SMEM>>>(
        h, wf1, ffn_b1, nullptr, ff, M, 1024, 4096);
    // 9) out = x1 + ff @ wf2 + ffn_b2
    gemm_tc<true,false,true,false><<<dim3(1024/128, M/128), thr, GEMM_SMEM>>>(
        ff, wf2, ffn_b2, x1, out, M, 4096, 1024);
}

// round 3
// speedup vs baseline: 6.2721x; 4.1172x over previous
#include <cuda_runtime.h>
#include <math.h>
#include <stdint.h>

#define ROWS_T 4096
#define SEQ    2048
#define NHEADS 16

// ---------------- scratch ----------------------------------------------------
__device__ float g_gb   [ROWS_T * 2048];
__device__ float g_h    [ROWS_T * 1024];
__device__ float g_qkv  [ROWS_T * 3072];
__device__ float g_attnO[ROWS_T * 1024];
__device__ float g_x1   [ROWS_T * 1024];
__device__ float g_ff   [ROWS_T * 4096];
__device__ float g_sc   [ROWS_T * 512];
__device__ float g_w1   [512 * 2048];
__device__ float g_wqkv [1024 * 3072];
__device__ float g_wao  [1024 * 1024];
__device__ float g_w2   [512 * 2048];
__device__ float g_wf1  [1024 * 4096];
__device__ float g_wf2  [4096 * 1024];

__device__ __forceinline__ float rtf32(float x) {
    float y;
    asm("cvt.rna.tf32.f32 %0, %1;" : "=f"(y) : "f"(x));
    return y;
}

// ---------------- prep kernels ----------------------------------------------
__global__ void round_k(const float* __restrict__ in, float* __restrict__ out, int n4) {
    int i = blockIdx.x * blockDim.x + threadIdx.x;
    if (i < n4) {
        float4 v = reinterpret_cast<const float4*>(in)[i];
        v.x = rtf32(v.x); v.y = rtf32(v.y); v.z = rtf32(v.z); v.w = rtf32(v.w);
        reinterpret_cast<float4*>(out)[i] = v;
    }
}
__global__ void silu_round_k(const float* __restrict__ in, float* __restrict__ out, int n4) {
    int i = blockIdx.x * blockDim.x + threadIdx.x;
    if (i < n4) {
        float4 v = reinterpret_cast<const float4*>(in)[i];
        v.x = rtf32(v.x / (1.f + __expf(-v.x)));
        v.y = rtf32(v.y / (1.f + __expf(-v.y)));
        v.z = rtf32(v.z / (1.f + __expf(-v.z)));
        v.w = rtf32(v.w / (1.f + __expf(-v.w)));
        reinterpret_cast<float4*>(out)[i] = v;
    }
}

// ---------------- tf32 tensor-core GEMM --------------------------------------
#define AS_STG (128 * 36)
#define BS_STG (32 * 136)
#define GEMM_SMEM ((2 * AS_STG + 2 * BS_STG) * 4)

#define MMA_TF32(d, a, b) asm volatile( \
    "mma.sync.aligned.m16n8k8.row.col.f32.tf32.tf32.f32 " \
    "{%0,%1,%2,%3}, {%4,%5,%6,%7}, {%8,%9}, {%0,%1,%2,%3};" \
    : "+f"(d[0]), "+f"(d[1]), "+f"(d[2]), "+f"(d[3]) \
    : "r"(a[0]), "r"(a[1]), "r"(a[2]), "r"(a[3]), "r"(b[0]), "r"(b[1]))

#define CP16(dst_u32, src_ptr) asm volatile( \
    "cp.async.ca.shared.global [%0], [%1], 16;" :: "r"(dst_u32), "l"(src_ptr))

template<bool BIAS, bool GELU, bool RESID, bool ROUND>
__global__ void __launch_bounds__(256, 2) gemm_tc(
    const float* __restrict__ A, const float* __restrict__ W,
    const float* __restrict__ bias, const float* __restrict__ resid,
    float* __restrict__ C, int M, int K, int N)
{
    extern __shared__ float sm[];
    float* As = sm;
    float* Bs = sm + 2 * AS_STG;

    uint32_t smem_base;
    asm("{.reg .u64 t; cvta.to.shared.u64 t, %1; cvt.u32.u64 %0, t;}"
        : "=r"(smem_base) : "l"(sm));
    const uint32_t asb = smem_base;
    const uint32_t bsb = smem_base + 2 * AS_STG * 4;

    const int tid  = threadIdx.x;
    const int lane = tid & 31;
    const int warp = tid >> 5;
    const int wm = (warp & 1) * 64;
    const int wn = (warp >> 1) * 32;
    const int gid = lane >> 2;
    const int tig = lane & 3;

    const int m0 = blockIdx.y * 128;
    const int n0 = blockIdx.x * 128;

    const int a_m = tid >> 3;
    const int a_k = (tid & 7) << 2;
    const int b_k = tid >> 5;
    const int b_n = (tid & 31) << 2;

    float acc[4][4][4];
#pragma unroll
    for (int i = 0; i < 4; i++)
#pragma unroll
        for (int j = 0; j < 4; j++)
#pragma unroll
            for (int r = 0; r < 4; r++) acc[i][j][r] = 0.f;

    const int nt = K >> 5;

#pragma unroll
    for (int i = 0; i < 4; i++) {
        CP16(asb + ((a_m + i * 32) * 36 + a_k) * 4,
             A + (size_t)(m0 + a_m + i * 32) * K + a_k);
        CP16(bsb + ((b_k + i * 8) * 136 + b_n) * 4,
             W + (size_t)(b_k + i * 8) * N + n0 + b_n);
    }
    asm volatile("cp.async.commit_group;");

    for (int t = 0; t < nt; t++) {
        const int cur = t & 1;
        if (t + 1 < nt) {
            const int nk0 = (t + 1) << 5;
            const int st = cur ^ 1;
#pragma unroll
            for (int i = 0; i < 4; i++) {
                CP16(asb + (st * AS_STG + (a_m + i * 32) * 36 + a_k) * 4,
                     A + (size_t)(m0 + a_m + i * 32) * K + nk0 + a_k);
                CP16(bsb + (st * BS_STG + (b_k + i * 8) * 136 + b_n) * 4,
                     W + (size_t)(nk0 + b_k + i * 8) * N + n0 + b_n);
            }
            asm volatile("cp.async.commit_group;");
            asm volatile("cp.async.wait_group 1;");
        } else {
            asm volatile("cp.async.wait_group 0;");
        }
        __syncthreads();

        const float* Asw = As + cur * AS_STG + wm * 36;
        const float* Bsw = Bs + cur * BS_STG + wn;
#pragma unroll
        for (int s = 0; s < 4; s++) {
            uint32_t af[4][4], bf[4][2];
#pragma unroll
            for (int mt = 0; mt < 4; mt++) {
                const float* p = Asw + (mt * 16 + gid) * 36 + s * 8 + tig;
                af[mt][0] = __float_as_uint(p[0]);
                af[mt][1] = __float_as_uint(p[8 * 36]);
                af[mt][2] = __float_as_uint(p[4]);
                af[mt][3] = __float_as_uint(p[8 * 36 + 4]);
            }
#pragma unroll
            for (int ntile = 0; ntile < 4; ntile++) {
                const float* p = Bsw + (s * 8 + tig) * 136 + ntile * 8 + gid;
                bf[ntile][0] = __float_as_uint(p[0]);
                bf[ntile][1] = __float_as_uint(p[4 * 136]);
            }
#pragma unroll
            for (int mt = 0; mt < 4; mt++)
#pragma unroll
                for (int ntile = 0; ntile < 4; ntile++)
                    MMA_TF32(acc[mt][ntile], af[mt], bf[ntile]);
        }
        __syncthreads();
    }

#pragma unroll
    for (int mt = 0; mt < 4; mt++) {
        const int r0 = m0 + wm + mt * 16 + gid;
#pragma unroll
        for (int ntile = 0; ntile < 4; ntile++) {
            const int col = n0 + wn + ntile * 8 + 2 * tig;
            float b0 = 0.f, b1 = 0.f;
            if (BIAS) { b0 = bias[col]; b1 = bias[col + 1]; }
#pragma unroll
            for (int half = 0; half < 2; half++) {
                const int row = r0 + half * 8;
                float v0 = acc[mt][ntile][half * 2 + 0] + b0;
                float v1 = acc[mt][ntile][half * 2 + 1] + b1;
                if (GELU) {
                    v0 = 0.5f * v0 * (1.f + erff(v0 * 0.70710678118654752f));
                    v1 = 0.5f * v1 * (1.f + erff(v1 * 0.70710678118654752f));
                }
                if (RESID) {
                    v0 += resid[(size_t)row * N + col];
                    v1 += resid[(size_t)row * N + col + 1];
                }
                if (ROUND) { v0 = rtf32(v0); v1 = rtf32(v1); }
                float2 o = {v0, v1};
                *reinterpret_cast<float2*>(C + (size_t)row * N + col) = o;
            }
        }
    }
}

// ---------------- AdaLN ------------------------------------------------------
__global__ void __launch_bounds__(256) adaln_k(
    const float* __restrict__ x, const float* __restrict__ gb,
    float* __restrict__ out)
{
    const int row = blockIdx.x;
    const int tid = threadIdx.x;
    const float4* xr = reinterpret_cast<const float4*>(x + (size_t)row * 1024);
    float4 v = xr[tid];

    float s  = v.x + v.y + v.z + v.w;
    float ss = v.x * v.x + v.y * v.y + v.z * v.z + v.w * v.w;
#pragma unroll
    for (int o = 16; o > 0; o >>= 1) {
        s  += __shfl_xor_sync(0xffffffffu, s,  o);
        ss += __shfl_xor_sync(0xffffffffu, ss, o);
    }
    __shared__ float rs[8], rss[8];
    const int w = tid >> 5, l = tid & 31;
    if (l == 0) { rs[w] = s; rss[w] = ss; }
    __syncthreads();
    if (w == 0) {
        s  = (l < 8) ? rs[l]  : 0.f;
        ss = (l < 8) ? rss[l] : 0.f;
#pragma unroll
        for (int o = 4; o > 0; o >>= 1) {
            s  += __shfl_xor_sync(0xffffffffu, s,  o);
            ss += __shfl_xor_sync(0xffffffffu, ss, o);
        }
        if (l == 0) { rs[0] = s; rss[0] = ss; }
    }
    __syncthreads();
    const float mean = rs[0] * (1.f / 1024.f);
    const float var  = rss[0] * (1.f / 1024.f) - mean * mean;
    const float rstd = rsqrtf(var + 1e-5f);

    const float4* gr = reinterpret_cast<const float4*>(gb + (size_t)row * 2048);
    float4 gm = gr[tid];
    float4 bt = gr[256 + tid];
    float4 o;
    o.x = rtf32((v.x - mean) * rstd * (1.f + gm.x) + bt.x);
    o.y = rtf32((v.y - mean) * rstd * (1.f + gm.y) + bt.y);
    o.z = rtf32((v.z - mean) * rstd * (1.f + gm.z) + bt.z);
    o.w = rtf32((v.w - mean) * rstd * (1.f + gm.w) + bt.w);
    reinterpret_cast<float4*>(out + (size_t)row * 1024)[tid] = o;
}

// ---------------- tensor-core flash attention --------------------------------
// qtile=128 (8 warps x 16 rows), kv tile=64, double-buffered cp.async.
// Ks[2][64][68], Vs[2][64][72], Ps[128][68] (warp-private rows).
#define FA2_KS_STG (64 * 68)
#define FA2_VS_STG (64 * 72)
#define FA2_PS_OFF (2 * FA2_KS_STG + 2 * FA2_VS_STG)
#define FA2_SMEM ((FA2_PS_OFF + 128 * 68) * 4)

__global__ void __launch_bounds__(256) fattn_tc(
    const float* __restrict__ qkv, float* __restrict__ out)
{
    extern __shared__ float sm[];
    float* Ks = sm;
    float* Vs = sm + 2 * FA2_KS_STG;
    float* Ps = sm + FA2_PS_OFF;

    uint32_t smb;
    asm("{.reg .u64 t; cvta.to.shared.u64 t, %1; cvt.u32.u64 %0, t;}"
        : "=r"(smb) : "l"(sm));
    const uint32_t ksb = smb;
    const uint32_t vsb = smb + 2 * FA2_KS_STG * 4;

    const int tid  = threadIdx.x;
    const int lane = tid & 31;
    const int warp = tid >> 5;
    const int gid  = lane >> 2;
    const int tig  = lane & 3;
    const int wm   = warp * 16;

    const int b = blockIdx.z, h = blockIdx.y;
    const int q0 = blockIdx.x * 128;
    const float* qbase = qkv + (size_t)b * SEQ * 3072 + h * 64;
    const float* kbase = qbase + 1024;
    const float* vbase = qbase + 2048;

    const int lr = tid >> 2;          // kv row 0..63
    const int lc = (tid & 3) * 4;     // float col base

    // issue KV tile 0 -> stage 0
#pragma unroll
    for (int i = 0; i < 4; i++) {
        const int c = lc + 16 * i;
        CP16(ksb + (lr * 68 + c) * 4, kbase + (size_t)lr * 3072 + c);
        CP16(vsb + (lr * 72 + c) * 4, vbase + (size_t)lr * 3072 + c);
    }
    asm volatile("cp.async.commit_group;");

    // stage Q (pre-scaled by 0.125) into Ps
    {
        const int row = tid >> 1;
        const float* qp = qbase + (size_t)(q0 + row) * 3072 + (tid & 1) * 32;
        float* pp = Ps + row * 68 + (tid & 1) * 32;
#pragma unroll
        for (int i = 0; i < 8; i++) {
            float4 v = *reinterpret_cast<const float4*>(qp + i * 4);
            v.x *= 0.125f; v.y *= 0.125f; v.z *= 0.125f; v.w *= 0.125f;
            *reinterpret_cast<float4*>(pp + i * 4) = v;
        }
    }
    __syncthreads();

    // Q fragments (registers, whole kernel)
    uint32_t qf[8][4];
#pragma unroll
    for (int s = 0; s < 8; s++) {
        const float* p = Ps + (wm + gid) * 68 + s * 8 + tig;
        qf[s][0] = __float_as_uint(p[0]);
        qf[s][1] = __float_as_uint(p[8 * 68]);
        qf[s][2] = __float_as_uint(p[4]);
        qf[s][3] = __float_as_uint(p[8 * 68 + 4]);
    }

    float oacc[8][4];
#pragma unroll
    for (int i = 0; i < 8; i++)
#pragma unroll
        for (int j = 0; j < 4; j++) oacc[i][j] = 0.f;
    float m0 = -3.0e38f, m1 = -3.0e38f, l0 = 0.f, l1 = 0.f;

    for (int t = 0; t < 32; t++) {
        const int cur = t & 1;
        if (t + 1 < 32) {
            const int st = cur ^ 1;
            const size_t roff = (size_t)((t + 1) * 64);
#pragma unroll
            for (int i = 0; i < 4; i++) {
                const int c = lc + 16 * i;
                CP16(ksb + (st * FA2_KS_STG + lr * 68 + c) * 4,
                     kbase + (roff + lr) * 3072 + c);
                CP16(vsb + (st * FA2_VS_STG + lr * 72 + c) * 4,
                     vbase + (roff + lr) * 3072 + c);
            }
            asm volatile("cp.async.commit_group;");
            asm volatile("cp.async.wait_group 1;");
        } else {
            asm volatile("cp.async.wait_group 0;");
        }
        __syncthreads();

        // S = Q @ K^T
        const float* Kc = Ks + cur * FA2_KS_STG;
        float sacc[8][4];
#pragma unroll
        for (int i = 0; i < 8; i++)
#pragma unroll
            for (int j = 0; j < 4; j++) sacc[i][j] = 0.f;
#pragma unroll
        for (int s = 0; s < 8; s++) {
#pragma unroll
            for (int nt = 0; nt < 8; nt++) {
                const float* p = Kc + (nt * 8 + gid) * 68 + s * 8 + tig;
                uint32_t bf[2];
                bf[0] = __float_as_uint(p[0]);
                bf[1] = __float_as_uint(p[4]);
                MMA_TF32(sacc[nt], qf[s], bf);
            }
        }

        // streaming softmax (rows wm+gid and wm+gid+8)
        float tm0 = -3.0e38f, tm1 = -3.0e38f;
#pragma unroll
        for (int nt = 0; nt < 8; nt++) {
            tm0 = fmaxf(tm0, fmaxf(sacc[nt][0], sacc[nt][1]));
            tm1 = fmaxf(tm1, fmaxf(sacc[nt][2], sacc[nt][3]));
        }
        tm0 = fmaxf(tm0, __shfl_xor_sync(0xffffffffu, tm0, 1));
        tm0 = fmaxf(tm0, __shfl_xor_sync(0xffffffffu, tm0, 2));
        tm1 = fmaxf(tm1, __shfl_xor_sync(0xffffffffu, tm1, 1));
        tm1 = fmaxf(tm1, __shfl_xor_sync(0xffffffffu, tm1, 2));

        const float mn0 = fmaxf(m0, tm0);
        const float mn1 = fmaxf(m1, tm1);
        const float cr0 = __expf(m0 - mn0);
        const float cr1 = __expf(m1 - mn1);
        m0 = mn0; m1 = mn1;

        float ts0 = 0.f, ts1 = 0.f;
        float* Pw = Ps + (wm + gid) * 68;
#pragma unroll
        for (int nt = 0; nt < 8; nt++) {
            float p0 = rtf32(__expf(sacc[nt][0] - mn0));
            float p1 = rtf32(__expf(sacc[nt][1] - mn0));
            float p2 = rtf32(__expf(sacc[nt][2] - mn1));
            float p3 = rtf32(__expf(sacc[nt][3] - mn1));
            ts0 += p0 + p1;
            ts1 += p2 + p3;
            float2 w0 = {p0, p1};
            float2 w1 = {p2, p3};
            *reinterpret_cast<float2*>(Pw + nt * 8 + 2 * tig) = w0;
            *reinterpret_cast<float2*>(Pw + 8 * 68 + nt * 8 + 2 * tig) = w1;
        }
        ts0 += __shfl_xor_sync(0xffffffffu, ts0, 1);
        ts0 += __shfl_xor_sync(0xffffffffu, ts0, 2);
        ts1 += __shfl_xor_sync(0xffffffffu, ts1, 1);
        ts1 += __shfl_xor_sync(0xffffffffu, ts1, 2);
        l0 = l0 * cr0 + ts0;
        l1 = l1 * cr1 + ts1;

#pragma unroll
        for (int nt = 0; nt < 8; nt++) {
            oacc[nt][0] *= cr0; oacc[nt][1] *= cr0;
            oacc[nt][2] *= cr1; oacc[nt][3] *= cr1;
        }
        __syncwarp();

        // O += P @ V
        const float* Vc = Vs + cur * FA2_VS_STG;
#pragma unroll
        for (int s = 0; s < 8; s++) {
            uint32_t af[4];
            const float* pa = Ps + (wm + gid) * 68 + s * 8 + tig;
            af[0] = __float_as_uint(pa[0]);
            af[1] = __float_as_uint(pa[8 * 68]);
            af[2] = __float_as_uint(pa[4]);
            af[3] = __float_as_uint(pa[8 * 68 + 4]);
#pragma unroll
            for (int nt = 0; nt < 8; nt++) {
                const float* pb = Vc + (s * 8 + tig) * 72 + nt * 8 + gid;
                uint32_t bf[2];
                bf[0] = __float_as_uint(pb[0]);
                bf[1] = __float_as_uint(pb[4 * 72]);
                MMA_TF32(oacc[nt], af, bf);
            }
        }
        __syncthreads();
    }

    const float inv0 = 1.f / l0;
    const float inv1 = 1.f / l1;
    const size_t orow0 = (size_t)(b * SEQ + q0 + wm + gid);
    const size_t orow1 = orow0 + 8;
#pragma unroll
    for (int nt = 0; nt < 8; nt++) {
        const int col = h * 64 + nt * 8 + 2 * tig;
        float2 o0 = {rtf32(oacc[nt][0] * inv0), rtf32(oacc[nt][1] * inv0)};
        float2 o1 = {rtf32(oacc[nt][2] * inv1), rtf32(oacc[nt][3] * inv1)};
        *reinterpret_cast<float2*>(out + orow0 * 1024 + col) = o0;
        *reinterpret_cast<float2*>(out + orow1 * 1024 + col) = o1;
    }
}

// ---------------- launch -----------------------------------------------------
extern "C" void kernel_launch(void* const* d_in, const int* in_sizes, int n_in,
                              void* d_out, int out_size)
{
    const float* x          = (const float*)d_in[0];
    const float* cond       = (const float*)d_in[1];
    const float* p1_w       = (const float*)d_in[2];
    const float* p1_b       = (const float*)d_in[3];
    const float* qkv_w      = (const float*)d_in[4];
    const float* attn_out_w = (const float*)d_in[5];
    const float* p2_w       = (const float*)d_in[6];
    const float* p2_b       = (const float*)d_in[7];
    const float* ffn_w1     = (const float*)d_in[8];
    const float* ffn_b1     = (const float*)d_in[9];
    const float* ffn_w2     = (const float*)d_in[10];
    const float* ffn_b2     = (const float*)d_in[11];
    float* out = (float*)d_out;

    float *gb, *h, *qkvb, *attnO, *x1, *ff, *sc;
    float *w1, *wqkv, *wao, *w2, *wf1, *wf2;
    cudaGetSymbolAddress((void**)&gb,    g_gb);
    cudaGetSymbolAddress((void**)&h,     g_h);
    cudaGetSymbolAddress((void**)&qkvb,  g_qkv);
    cudaGetSymbolAddress((void**)&attnO, g_attnO);
    cudaGetSymbolAddress((void**)&x1,    g_x1);
    cudaGetSymbolAddress((void**)&ff,    g_ff);
    cudaGetSymbolAddress((void**)&sc,    g_sc);
    cudaGetSymbolAddress((void**)&w1,    g_w1);
    cudaGetSymbolAddress((void**)&wqkv,  g_wqkv);
    cudaGetSymbolAddress((void**)&wao,   g_wao);
    cudaGetSymbolAddress((void**)&w2,    g_w2);
    cudaGetSymbolAddress((void**)&wf1,   g_wf1);
    cudaGetSymbolAddress((void**)&wf2,   g_wf2);

    cudaFuncSetAttribute(fattn_tc, cudaFuncAttributeMaxDynamicSharedMemorySize, FA2_SMEM);
    cudaFuncSetAttribute(gemm_tc<true,false,false,false>,
                         cudaFuncAttributeMaxDynamicSharedMemorySize, GEMM_SMEM);
    cudaFuncSetAttribute(gemm_tc<false,false,false,true>,
                         cudaFuncAttributeMaxDynamicSharedMemorySize, GEMM_SMEM);
    cudaFuncSetAttribute(gemm_tc<false,false,true,false>,
                         cudaFuncAttributeMaxDynamicSharedMemorySize, GEMM_SMEM);
    cudaFuncSetAttribute(gemm_tc<true,true,false,true>,
                         cudaFuncAttributeMaxDynamicSharedMemorySize, GEMM_SMEM);
    cudaFuncSetAttribute(gemm_tc<true,false,true,false>,
                         cudaFuncAttributeMaxDynamicSharedMemorySize, GEMM_SMEM);

    const int M = ROWS_T;
    const dim3 thr(256);

    round_k<<<(512*2048/4 + 255)/256, 256>>>(p1_w, w1, 512*2048/4);
    round_k<<<(1024*3072/4 + 255)/256, 256>>>(qkv_w, wqkv, 1024*3072/4);
    round_k<<<(1024*1024/4 + 255)/256, 256>>>(attn_out_w, wao, 1024*1024/4);
    round_k<<<(512*2048/4 + 255)/256, 256>>>(p2_w, w2, 512*2048/4);
    round_k<<<(1024*4096/4 + 255)/256, 256>>>(ffn_w1, wf1, 1024*4096/4);
    round_k<<<(4096*1024/4 + 255)/256, 256>>>(ffn_w2, wf2, 4096*1024/4);
    silu_round_k<<<(M*512/4 + 255)/256, 256>>>(cond, sc, M*512/4);

    // 1) gb = sc @ w1 + p1_b
    gemm_tc<true,false,false,false><<<dim3(2048/128, M/128), thr, GEMM_SMEM>>>(
        sc, w1, p1_b, nullptr, gb, M, 512, 2048);
    // 2) h = adaln(x, gb)
    adaln_k<<<M, 256>>>(x, gb, h);
    // 3) qkv = rtf32(h @ wqkv)
    gemm_tc<false,false,false,true><<<dim3(3072/128, M/128), thr, GEMM_SMEM>>>(
        h, wqkv, nullptr, nullptr, qkvb, M, 1024, 3072);
    // 4) attnO = attention(qkv)  (tensor cores)
    fattn_tc<<<dim3(SEQ/128, NHEADS, 2), thr, FA2_SMEM>>>(qkvb, attnO);
    // 5) x1 = x + attnO @ wao
    gemm_tc<false,false,true,false><<<dim3(1024/128, M/128), thr, GEMM_SMEM>>>(
        attnO, wao, nullptr, x, x1, M, 1024, 1024);
    // 6) gb = sc @ w2 + p2_b
    gemm_tc<true,false,false,false><<<dim3(2048/128, M/128), thr, GEMM_SMEM>>>(
        sc, w2, p2_b, nullptr, gb, M, 512, 2048);
    // 7) h = adaln(x1, gb)
    adaln_k<<<M, 256>>>(x1, gb, h);
    // 8) ff = rtf32(gelu(h @ wf1 + ffn_b1))
    gemm_tc<true,true,false,true><<<dim3(4096/128, M/128), thr, GEMM_SMEM>>>(
        h, wf1, ffn_b1, nullptr, ff, M, 1024, 4096);
    // 9) out = x1 + ff @ wf2 + ffn_b2
    gemm_tc<true,false,true,false><<<dim3(1024/128, M/128), thr, GEMM_SMEM>>>(
        ff, wf2, ffn_b2, x1, out, M, 4096, 1024);
}